// round 1
// baseline (speedup 1.0000x reference)
#include <cuda_runtime.h>
#include <math.h>
#include <stdint.h>

// Problem constants (fixed by the reference)
#define HD    128
#define HQ    32
#define HKV   8
#define SEQ   4096
#define BQ    128
#define BKV   128
#define WIN   512
#define CAPV  50.0f
#define EPSV  1e-5f
#define SCL   0.08838834764831845f   // 1/sqrt(128)

// Shared memory strides (floats)
#define QT_STRIDE 68    // QsT: [128 d][64 i + pad]
#define KT_STRIDE 132   // KsT: [128 d][128 j + pad]
#define VS_STRIDE 132   // Vs : [128 j][128 d + pad]
#define PS_STRIDE 132   // Ps : [64 i][128 j + pad]

#define BUFA_FLOATS 8704    // max(128*68, 64*132)
#define BUFB_FLOATS 16896   // 128*132
#define SMEM_FLOATS (BUFA_FLOATS + BUFB_FLOATS + 128)

#define ROWS_PER_CHUNK 8

__device__ int g_chunk_counter;

__global__ void init_counter_kernel() { g_chunk_counter = 0; }

__device__ __forceinline__ float warpSum(float v) {
    #pragma unroll
    for (int o = 16; o; o >>= 1) v += __shfl_xor_sync(0xffffffffu, v, o);
    return v;
}
__device__ __forceinline__ float warpMax(float v) {
    #pragma unroll
    for (int o = 16; o; o >>= 1) v = fmaxf(v, __shfl_xor_sync(0xffffffffu, v, o));
    return v;
}

__global__ __launch_bounds__(256, 2)
void oswa_fused_kernel(
    const float* __restrict__ q,   const float* __restrict__ k,
    const float* __restrict__ v,   const float* __restrict__ go,
    const float* __restrict__ glse,
    const float* __restrict__ gq,  const float* __restrict__ gk,
    const int* __restrict__ biq,   const int* __restrict__ bikv,
    float* __restrict__ out,
    int B, int nComputeBlocks, int nChunkO, int nChunkTotal)
{
    extern __shared__ float sm[];
    float* bufA = sm;                       // QsT then Ps
    float* bufB = sm + BUFA_FLOATS;         // KsT then Vs
    float* smax = sm + BUFA_FLOATS + BUFB_FLOATS;   // [64]
    float* slse = smax + 64;                        // [64]
    __shared__ int s_chunk;

    const int t    = threadIdx.x;
    const int lane = t & 31;
    const int w    = t >> 5;

    const int bidq  = biq[0];
    const int bidkv = bikv[0];
    const int row0  = bidq * BQ;
    const size_t O_ELEMS = (size_t)B * SEQ * HQ * HD;

    const int bid = blockIdx.x;

    if (bid < nComputeBlocks) {
        // ---------------- attention tile: (batch, head, q-half of 64 rows) ----------------
        const int half  = bid & 1;
        const int h     = (bid >> 1) % HQ;
        const int batch = bid / (2 * HQ);
        const int kh    = h / (HQ / HKV);

        // ---- load+RMSNorm K -> KsT[d][j]  (warp w handles rows w*16 .. w*16+15) ----
        {
            const float4 g4 = *(const float4*)(gk + kh * HD + lane * 4);
            const float gv[4] = {g4.x, g4.y, g4.z, g4.w};
            #pragma unroll 4
            for (int jj = 0; jj < 16; jj++) {
                const int j = w * 16 + jj;
                const float4 kv4 = *(const float4*)(k + (((size_t)batch * BKV + j) * HKV + kh) * HD + lane * 4);
                float ss = kv4.x * kv4.x + kv4.y * kv4.y + kv4.z * kv4.z + kv4.w * kv4.w;
                ss = warpSum(ss);
                const float rstd = rsqrtf(ss * (1.0f / HD) + EPSV);
                const float kv[4] = {kv4.x, kv4.y, kv4.z, kv4.w};
                #pragma unroll
                for (int e = 0; e < 4; e++) {
                    const int jr = (e + lane) & 3;           // rotate to reduce STS conflicts
                    const int d  = lane * 4 + jr;
                    bufB[d * KT_STRIDE + j] = kv[jr] * rstd * gv[jr];
                }
            }
        }
        // ---- load+RMSNorm Q -> QsT[d][i]  (warp w handles local rows w*8 .. w*8+7) ----
        {
            const float4 g4 = *(const float4*)(gq + h * HD + lane * 4);
            const float gv[4] = {g4.x, g4.y, g4.z, g4.w};
            #pragma unroll 4
            for (int ii = 0; ii < 8; ii++) {
                const int i    = w * 8 + ii;
                const int qrow = half * 64 + i;
                const float4 qv4 = *(const float4*)(q + (((size_t)batch * BQ + qrow) * HQ + h) * HD + lane * 4);
                float ss = qv4.x * qv4.x + qv4.y * qv4.y + qv4.z * qv4.z + qv4.w * qv4.w;
                ss = warpSum(ss);
                const float rstd = rsqrtf(ss * (1.0f / HD) + EPSV);
                const float qv[4] = {qv4.x, qv4.y, qv4.z, qv4.w};
                #pragma unroll
                for (int e = 0; e < 4; e++) {
                    const int jr = (e + lane) & 3;
                    const int d  = lane * 4 + jr;
                    bufA[d * QT_STRIDE + i] = qv[jr] * rstd * gv[jr];
                }
            }
        }
        __syncthreads();

        // ---- GEMM1: S[64][128] = QsT^T * KsT  (thread: 4 rows x 8 cols) ----
        const int i0 = (t >> 4) * 4;       // 0..60
        const int c0 = (t & 15) * 8;       // 0..120
        float acc[4][8];
        #pragma unroll
        for (int r = 0; r < 4; r++)
            #pragma unroll
            for (int c = 0; c < 8; c++) acc[r][c] = 0.0f;

        #pragma unroll 4
        for (int d = 0; d < HD; d++) {
            const float4 a4 = *(const float4*)&bufA[d * QT_STRIDE + i0];
            const float4 b0 = *(const float4*)&bufB[d * KT_STRIDE + c0];
            const float4 b1 = *(const float4*)&bufB[d * KT_STRIDE + c0 + 4];
            const float a[4] = {a4.x, a4.y, a4.z, a4.w};
            const float b[8] = {b0.x, b0.y, b0.z, b0.w, b1.x, b1.y, b1.z, b1.w};
            #pragma unroll
            for (int r = 0; r < 4; r++)
                #pragma unroll
                for (int c = 0; c < 8; c++) acc[r][c] = fmaf(a[r], b[c], acc[r][c]);
        }
        __syncthreads();   // all done reading bufA/bufB

        // ---- cap + mask -> Ps (bufA) ; cooperative V load -> Vs (bufB) ----
        #pragma unroll
        for (int r = 0; r < 4; r++) {
            const int qi = row0 + half * 64 + i0 + r;
            #pragma unroll
            for (int c = 0; c < 8; c++) {
                const int kj = bidkv * BKV + c0 + c;
                const float lg = CAPV * tanhf(acc[r][c] * (SCL / CAPV));
                const bool allowed = (kj <= qi) && (kj >= qi - WIN) && (qi < SEQ) && (kj < SEQ);
                bufA[(i0 + r) * PS_STRIDE + c0 + c] = allowed ? lg : -INFINITY;
            }
        }
        #pragma unroll 4
        for (int idx = t; idx < BKV * (HD / 4); idx += 256) {
            const int j  = idx >> 5;
            const int c4 = idx & 31;
            const float4 vv = *(const float4*)(v + (((size_t)batch * BKV + j) * HKV + kh) * HD + c4 * 4);
            *(float4*)&bufB[j * VS_STRIDE + c4 * 4] = vv;
        }
        __syncthreads();

        // ---- row softmax (warp w handles rows w*8 .. w*8+7) ----
        #pragma unroll
        for (int rr = 0; rr < 8; rr++) {
            const int row = w * 8 + rr;
            float x0 = bufA[row * PS_STRIDE + lane];
            float x1 = bufA[row * PS_STRIDE + lane + 32];
            float x2 = bufA[row * PS_STRIDE + lane + 64];
            float x3 = bufA[row * PS_STRIDE + lane + 96];
            float m = warpMax(fmaxf(fmaxf(x0, x1), fmaxf(x2, x3)));
            float e0, e1, e2, e3;
            if (m == -INFINITY) { e0 = e1 = e2 = e3 = 0.0f; }
            else {
                e0 = expf(x0 - m); e1 = expf(x1 - m);
                e2 = expf(x2 - m); e3 = expf(x3 - m);
            }
            const float ssum = warpSum(e0 + e1 + e2 + e3);
            bufA[row * PS_STRIDE + lane]      = e0;
            bufA[row * PS_STRIDE + lane + 32] = e1;
            bufA[row * PS_STRIDE + lane + 64] = e2;
            bufA[row * PS_STRIDE + lane + 96] = e3;
            if (lane == 0) {
                smax[row] = m;
                slse[row] = (ssum > 0.0f) ? (m + logf(ssum)) : -INFINITY;
            }
        }
        __syncthreads();

        // ---- GEMM2: Ounnorm[64][128] = Ps * Vs  (thread: 4 rows x 8 d-cols) ----
        float acc2[4][8];
        #pragma unroll
        for (int r = 0; r < 4; r++)
            #pragma unroll
            for (int c = 0; c < 8; c++) acc2[r][c] = 0.0f;

        #pragma unroll 4
        for (int j = 0; j < BKV; j++) {
            float a[4];
            #pragma unroll
            for (int r = 0; r < 4; r++) a[r] = bufA[(i0 + r) * PS_STRIDE + j];
            const float4 b0 = *(const float4*)&bufB[j * VS_STRIDE + c0];
            const float4 b1 = *(const float4*)&bufB[j * VS_STRIDE + c0 + 4];
            const float b[8] = {b0.x, b0.y, b0.z, b0.w, b1.x, b1.y, b1.z, b1.w};
            #pragma unroll
            for (int r = 0; r < 4; r++)
                #pragma unroll
                for (int c = 0; c < 8; c++) acc2[r][c] = fmaf(a[r], b[c], acc2[r][c]);
        }

        // ---- online merge + writeout ----
        #pragma unroll
        for (int r = 0; r < 4; r++) {
            const int row = i0 + r;
            const int s   = row0 + half * 64 + row;
            const float lse_old = glse[((size_t)batch * HQ + h) * SEQ + s];
            const float m  = smax[row];
            const float lb = slse[row];
            const float mx = fmaxf(lse_old, lb);
            const float lse_new = (mx == -INFINITY) ? -INFINITY
                                 : mx + log1pf(expf(fminf(lse_old, lb) - mx));
            const bool fin = isfinite(lse_new);
            const float c_old = fin ? expf(lse_old - lse_new) : 0.0f;
            const float cb    = fin ? expf(m - lse_new) : 0.0f;   // absorbs 1/sum

            const size_t base = (((size_t)batch * SEQ + s) * HQ + h) * HD + c0;
            const float4 o0 = *(const float4*)(go + base);
            const float4 o1 = *(const float4*)(go + base + 4);
            float4 w0, w1;
            w0.x = c_old * o0.x + cb * acc2[r][0];
            w0.y = c_old * o0.y + cb * acc2[r][1];
            w0.z = c_old * o0.z + cb * acc2[r][2];
            w0.w = c_old * o0.w + cb * acc2[r][3];
            w1.x = c_old * o1.x + cb * acc2[r][4];
            w1.y = c_old * o1.y + cb * acc2[r][5];
            w1.z = c_old * o1.z + cb * acc2[r][6];
            w1.w = c_old * o1.w + cb * acc2[r][7];
            *(float4*)(out + base)     = w0;
            *(float4*)(out + base + 4) = w1;

            if ((t & 15) == 0)
                out[O_ELEMS + ((size_t)batch * HQ + h) * SEQ + s] = lse_new;
        }
    }

    // ---------------- dynamic copy of the untouched output regions ----------------
    const float4* src_o = (const float4*)go;
    float4*       dst_o = (float4*)out;
    const float4* src_l = (const float4*)glse;
    float4*       dst_l = (float4*)(out + O_ELEMS);   // O_ELEMS % 4 == 0
    const int SROWS = SEQ - BQ;                       // 3968 copyable rows per batch

    while (true) {
        if (t == 0) s_chunk = atomicAdd(&g_chunk_counter, 1);
        __syncthreads();
        const int c = s_chunk;
        __syncthreads();
        if (c >= nChunkTotal) break;

        if (c < nChunkO) {
            // 8 full global_o rows (each 32*128 floats = 1024 float4)
            const int vr0 = c * ROWS_PER_CHUNK;
            #pragma unroll
            for (int rr = 0; rr < ROWS_PER_CHUNK; rr++) {
                const int vr    = vr0 + rr;
                const int batch = vr / SROWS;
                const int s0    = vr - batch * SROWS;
                const int s     = s0 + (s0 >= row0 ? BQ : 0);
                const size_t rb4 = (((size_t)batch * SEQ + s) * HQ * HD) >> 2;
                #pragma unroll
                for (int u = 0; u < 4; u++)
                    dst_o[rb4 + t + u * 256] = src_o[rb4 + t + u * 256];
            }
        } else {
            // one (batch,head) lse row, skipping the updated 128 positions
            const int hb = c - nChunkO;                 // 0 .. B*HQ-1
            const size_t base = (size_t)hb * SEQ;
            const int npos4 = SROWS >> 2;               // 992
            for (int p4 = t; p4 < npos4; p4 += 256) {
                const int p = p4 * 4;
                const int s = p + (p >= row0 ? BQ : 0); // row0 % 4 == 0 -> stays aligned
                dst_l[(base + s) >> 2] = src_l[(base + s) >> 2];
            }
        }
    }
}

extern "C" void kernel_launch(void* const* d_in, const int* in_sizes, int n_in,
                              void* d_out, int out_size)
{
    const float* q    = (const float*)d_in[0];
    const float* k    = (const float*)d_in[1];
    const float* v    = (const float*)d_in[2];
    const float* go   = (const float*)d_in[3];
    const float* glse = (const float*)d_in[4];
    const float* gq   = (const float*)d_in[5];
    const float* gk   = (const float*)d_in[6];
    const int*   biq  = (const int*)d_in[7];
    const int*   bikv = (const int*)d_in[8];
    float* out = (float*)d_out;

    const int B = in_sizes[0] / (BQ * HQ * HD);           // 4
    const int nCompute    = B * HQ * 2;                   // 256
    const int nChunkO     = (B * (SEQ - BQ)) / ROWS_PER_CHUNK; // 1984
    const int nChunkTotal = nChunkO + B * HQ;             // +128 lse chunks

    const size_t smem = SMEM_FLOATS * sizeof(float);      // ~100.5 KB
    cudaFuncSetAttribute(oswa_fused_kernel,
                         cudaFuncAttributeMaxDynamicSharedMemorySize, (int)smem);

    const int grid = nCompute + 40;   // 296 = 2 CTAs/SM * 148 SMs (fill with pure-copy CTAs)

    init_counter_kernel<<<1, 1>>>();
    oswa_fused_kernel<<<grid, 256, smem>>>(q, k, v, go, glse, gq, gk, biq, bikv,
                                           out, B, nCompute, nChunkO, nChunkTotal);
}

// round 2
// speedup vs baseline: 1.1675x; 1.1675x over previous
#include <cuda_runtime.h>
#include <math.h>
#include <stdint.h>

// Problem constants (fixed by the reference)
#define HD    128
#define HQ    32
#define HKV   8
#define SEQ   4096
#define BQ    128
#define BKV   128
#define WIN   512
#define CAPV  50.0f
#define EPSV  1e-5f
#define SCL   0.08838834764831845f   // 1/sqrt(128)

// Shared memory strides (floats)
#define QT_STRIDE 68    // QsT: [128 d][64 i + pad]
#define KT_STRIDE 132   // KsT: [128 d][128 j + pad]
#define VS_STRIDE 132   // Vs : [128 j][128 d + pad]
#define PS_STRIDE 132   // Ps : [64 i][128 j + pad]

#define BUFA_FLOATS 8704    // max(128*68, 64*132)
#define BUFB_FLOATS 16896   // 128*132
#define SMEM_FLOATS (BUFA_FLOATS + BUFB_FLOATS + 128)

#define ROWS_PER_CHUNK 8
#define N_PRE 5            // copy chunks a deferred compute CTA does before computing

__device__ int g_chunk_counter;

__global__ void init_counter_kernel() { g_chunk_counter = 0; }

__device__ __forceinline__ float warpSum(float v) {
    #pragma unroll
    for (int o = 16; o; o >>= 1) v += __shfl_xor_sync(0xffffffffu, v, o);
    return v;
}
__device__ __forceinline__ float warpMax(float v) {
    #pragma unroll
    for (int o = 16; o; o >>= 1) v = fmaxf(v, __shfl_xor_sync(0xffffffffu, v, o));
    return v;
}

struct CopyCtx {
    const float4* src_o;
    float4*       dst_o;
    const float4* src_l;
    float4*       dst_l;
    int row0;
    int nChunkO;
};

// Copy one chunk c. Chunks < nChunkO are 8 full global_o rows (128KB);
// the rest are one (batch,head) lse row each, skipping the updated slice.
__device__ __forceinline__ void copy_chunk(const CopyCtx& cc, int c, int t)
{
    const int SROWS = SEQ - BQ;   // 3968
    if (c < cc.nChunkO) {
        const int vr0 = c * ROWS_PER_CHUNK;
        #pragma unroll
        for (int rr = 0; rr < ROWS_PER_CHUNK; rr += 2) {
            const int vrA = vr0 + rr, vrB = vr0 + rr + 1;
            const int bA = vrA / SROWS, bB = vrB / SROWS;
            const int sA0 = vrA - bA * SROWS, sB0 = vrB - bB * SROWS;
            const int sA = sA0 + (sA0 >= cc.row0 ? BQ : 0);
            const int sB = sB0 + (sB0 >= cc.row0 ? BQ : 0);
            const size_t rbA = (((size_t)bA * SEQ + sA) * HQ * HD) >> 2;
            const size_t rbB = (((size_t)bB * SEQ + sB) * HQ * HD) >> 2;
            float4 tmp[8];
            #pragma unroll
            for (int u = 0; u < 4; u++) tmp[u]     = __ldcs(cc.src_o + rbA + t + u * 256);
            #pragma unroll
            for (int u = 0; u < 4; u++) tmp[4 + u] = __ldcs(cc.src_o + rbB + t + u * 256);
            #pragma unroll
            for (int u = 0; u < 4; u++) __stcs(cc.dst_o + rbA + t + u * 256, tmp[u]);
            #pragma unroll
            for (int u = 0; u < 4; u++) __stcs(cc.dst_o + rbB + t + u * 256, tmp[4 + u]);
        }
    } else {
        const int hb = c - cc.nChunkO;              // 0 .. B*HQ-1
        const size_t base = (size_t)hb * SEQ;
        const int npos4 = SROWS >> 2;               // 992
        for (int p4 = t; p4 < npos4; p4 += 256) {
            const int p = p4 * 4;
            const int s = p + (p >= cc.row0 ? BQ : 0); // row0 % 4 == 0 -> stays aligned
            __stcs(cc.dst_l + ((base + s) >> 2), __ldcs(cc.src_l + ((base + s) >> 2)));
        }
    }
}

__global__ __launch_bounds__(256, 2)
void oswa_fused_kernel(
    const float* __restrict__ q,   const float* __restrict__ k,
    const float* __restrict__ v,   const float* __restrict__ go,
    const float* __restrict__ glse,
    const float* __restrict__ gq,  const float* __restrict__ gk,
    const int* __restrict__ biq,   const int* __restrict__ bikv,
    float* __restrict__ out,
    int B, int nComputeBlocks, int nChunkO, int nChunkTotal)
{
    extern __shared__ float sm[];
    float* bufA = sm;                       // QsT then Ps
    float* bufB = sm + BUFA_FLOATS;         // KsT then Vs
    float* smax = sm + BUFA_FLOATS + BUFB_FLOATS;   // [64]
    float* slse = smax + 64;                        // [64]
    __shared__ int s_chunk;

    const int t    = threadIdx.x;
    const int lane = t & 31;
    const int w    = t >> 5;

    const int bidq  = biq[0];
    const int bidkv = bikv[0];
    const int row0  = bidq * BQ;
    const size_t O_ELEMS = (size_t)B * SEQ * HQ * HD;

    CopyCtx cc;
    cc.src_o = (const float4*)go;
    cc.dst_o = (float4*)out;
    cc.src_l = (const float4*)glse;
    cc.dst_l = (float4*)(out + O_ELEMS);
    cc.row0  = row0;
    cc.nChunkO = nChunkO;

    const int bid = blockIdx.x;

    if (bid < nComputeBlocks) {
        // ---- stagger: the second co-resident CTA on each SM (bid>=148) copies
        //      ~N_PRE chunks first so DRAM stays fed while its partner computes.
        if (bid >= 148) {
            for (int it = 0; it < N_PRE; it++) {
                if (t == 0) s_chunk = atomicAdd(&g_chunk_counter, 1);
                __syncthreads();
                const int c = s_chunk;
                __syncthreads();
                if (c < nChunkTotal) copy_chunk(cc, c, t);
                else break;
            }
        }

        // ---------------- attention tile: (batch, head, q-half of 64 rows) ----------------
        const int half  = bid & 1;
        const int h     = (bid >> 1) % HQ;
        const int batch = bid / (2 * HQ);
        const int kh    = h / (HQ / HKV);

        // ---- load+RMSNorm K -> KsT[d][j]  (warp w handles rows w*16 .. w*16+15) ----
        {
            const float4 g4 = *(const float4*)(gk + kh * HD + lane * 4);
            const float gv[4] = {g4.x, g4.y, g4.z, g4.w};
            #pragma unroll 4
            for (int jj = 0; jj < 16; jj++) {
                const int j = w * 16 + jj;
                const float4 kv4 = *(const float4*)(k + (((size_t)batch * BKV + j) * HKV + kh) * HD + lane * 4);
                float ss = kv4.x * kv4.x + kv4.y * kv4.y + kv4.z * kv4.z + kv4.w * kv4.w;
                ss = warpSum(ss);
                const float rstd = rsqrtf(ss * (1.0f / HD) + EPSV);
                const float kv[4] = {kv4.x, kv4.y, kv4.z, kv4.w};
                #pragma unroll
                for (int e = 0; e < 4; e++) {
                    const int jr = (e + lane) & 3;           // rotate to reduce STS conflicts
                    const int d  = lane * 4 + jr;
                    bufB[d * KT_STRIDE + j] = kv[jr] * rstd * gv[jr];
                }
            }
        }
        // ---- load+RMSNorm Q -> QsT[d][i]  (warp w handles local rows w*8 .. w*8+7) ----
        {
            const float4 g4 = *(const float4*)(gq + h * HD + lane * 4);
            const float gv[4] = {g4.x, g4.y, g4.z, g4.w};
            #pragma unroll 4
            for (int ii = 0; ii < 8; ii++) {
                const int i    = w * 8 + ii;
                const int qrow = half * 64 + i;
                const float4 qv4 = *(const float4*)(q + (((size_t)batch * BQ + qrow) * HQ + h) * HD + lane * 4);
                float ss = qv4.x * qv4.x + qv4.y * qv4.y + qv4.z * qv4.z + qv4.w * qv4.w;
                ss = warpSum(ss);
                const float rstd = rsqrtf(ss * (1.0f / HD) + EPSV);
                const float qv[4] = {qv4.x, qv4.y, qv4.z, qv4.w};
                #pragma unroll
                for (int e = 0; e < 4; e++) {
                    const int jr = (e + lane) & 3;
                    const int d  = lane * 4 + jr;
                    bufA[d * QT_STRIDE + i] = qv[jr] * rstd * gv[jr];
                }
            }
        }
        __syncthreads();

        // ---- GEMM1: S[64][128] = QsT^T * KsT  (thread: 4 rows x 8 cols) ----
        const int i0 = (t >> 4) * 4;       // 0..60
        const int c0 = (t & 15) * 8;       // 0..120
        float acc[4][8];
        #pragma unroll
        for (int r = 0; r < 4; r++)
            #pragma unroll
            for (int c = 0; c < 8; c++) acc[r][c] = 0.0f;

        #pragma unroll 4
        for (int d = 0; d < HD; d++) {
            const float4 a4 = *(const float4*)&bufA[d * QT_STRIDE + i0];
            const float4 b0 = *(const float4*)&bufB[d * KT_STRIDE + c0];
            const float4 b1 = *(const float4*)&bufB[d * KT_STRIDE + c0 + 4];
            const float a[4] = {a4.x, a4.y, a4.z, a4.w};
            const float b[8] = {b0.x, b0.y, b0.z, b0.w, b1.x, b1.y, b1.z, b1.w};
            #pragma unroll
            for (int r = 0; r < 4; r++)
                #pragma unroll
                for (int c = 0; c < 8; c++) acc[r][c] = fmaf(a[r], b[c], acc[r][c]);
        }
        __syncthreads();   // all done reading bufA/bufB

        // ---- cap + mask -> Ps (bufA) ; cooperative V load -> Vs (bufB) ----
        #pragma unroll
        for (int r = 0; r < 4; r++) {
            const int qi = row0 + half * 64 + i0 + r;
            #pragma unroll
            for (int c = 0; c < 8; c++) {
                const int kj = bidkv * BKV + c0 + c;
                const float lg = CAPV * tanhf(acc[r][c] * (SCL / CAPV));
                const bool allowed = (kj <= qi) && (kj >= qi - WIN) && (qi < SEQ) && (kj < SEQ);
                bufA[(i0 + r) * PS_STRIDE + c0 + c] = allowed ? lg : -INFINITY;
            }
        }
        #pragma unroll 4
        for (int idx = t; idx < BKV * (HD / 4); idx += 256) {
            const int j  = idx >> 5;
            const int c4 = idx & 31;
            const float4 vv = *(const float4*)(v + (((size_t)batch * BKV + j) * HKV + kh) * HD + c4 * 4);
            *(float4*)&bufB[j * VS_STRIDE + c4 * 4] = vv;
        }
        __syncthreads();

        // ---- row softmax (warp w handles rows w*8 .. w*8+7) ----
        #pragma unroll
        for (int rr = 0; rr < 8; rr++) {
            const int row = w * 8 + rr;
            float x0 = bufA[row * PS_STRIDE + lane];
            float x1 = bufA[row * PS_STRIDE + lane + 32];
            float x2 = bufA[row * PS_STRIDE + lane + 64];
            float x3 = bufA[row * PS_STRIDE + lane + 96];
            float m = warpMax(fmaxf(fmaxf(x0, x1), fmaxf(x2, x3)));
            float e0, e1, e2, e3;
            if (m == -INFINITY) { e0 = e1 = e2 = e3 = 0.0f; }
            else {
                e0 = expf(x0 - m); e1 = expf(x1 - m);
                e2 = expf(x2 - m); e3 = expf(x3 - m);
            }
            const float ssum = warpSum(e0 + e1 + e2 + e3);
            bufA[row * PS_STRIDE + lane]      = e0;
            bufA[row * PS_STRIDE + lane + 32] = e1;
            bufA[row * PS_STRIDE + lane + 64] = e2;
            bufA[row * PS_STRIDE + lane + 96] = e3;
            if (lane == 0) {
                smax[row] = m;
                slse[row] = (ssum > 0.0f) ? (m + logf(ssum)) : -INFINITY;
            }
        }
        __syncthreads();

        // ---- GEMM2: Ounnorm[64][128] = Ps * Vs  (thread: 4 rows x 8 d-cols) ----
        float acc2[4][8];
        #pragma unroll
        for (int r = 0; r < 4; r++)
            #pragma unroll
            for (int c = 0; c < 8; c++) acc2[r][c] = 0.0f;

        #pragma unroll 4
        for (int j = 0; j < BKV; j++) {
            float a[4];
            #pragma unroll
            for (int r = 0; r < 4; r++) a[r] = bufA[(i0 + r) * PS_STRIDE + j];
            const float4 b0 = *(const float4*)&bufB[j * VS_STRIDE + c0];
            const float4 b1 = *(const float4*)&bufB[j * VS_STRIDE + c0 + 4];
            const float b[8] = {b0.x, b0.y, b0.z, b0.w, b1.x, b1.y, b1.z, b1.w};
            #pragma unroll
            for (int r = 0; r < 4; r++)
                #pragma unroll
                for (int c = 0; c < 8; c++) acc2[r][c] = fmaf(a[r], b[c], acc2[r][c]);
        }

        // ---- online merge + writeout ----
        #pragma unroll
        for (int r = 0; r < 4; r++) {
            const int row = i0 + r;
            const int s   = row0 + half * 64 + row;
            const float lse_old = glse[((size_t)batch * HQ + h) * SEQ + s];
            const float m  = smax[row];
            const float lb = slse[row];
            const float mx = fmaxf(lse_old, lb);
            const float lse_new = (mx == -INFINITY) ? -INFINITY
                                 : mx + log1pf(expf(fminf(lse_old, lb) - mx));
            const bool fin = isfinite(lse_new);
            const float c_old = fin ? expf(lse_old - lse_new) : 0.0f;
            const float cb    = fin ? expf(m - lse_new) : 0.0f;   // absorbs 1/sum

            const size_t base = (((size_t)batch * SEQ + s) * HQ + h) * HD + c0;
            const float4 o0 = *(const float4*)(go + base);
            const float4 o1 = *(const float4*)(go + base + 4);
            float4 w0, w1;
            w0.x = c_old * o0.x + cb * acc2[r][0];
            w0.y = c_old * o0.y + cb * acc2[r][1];
            w0.z = c_old * o0.z + cb * acc2[r][2];
            w0.w = c_old * o0.w + cb * acc2[r][3];
            w1.x = c_old * o1.x + cb * acc2[r][4];
            w1.y = c_old * o1.y + cb * acc2[r][5];
            w1.z = c_old * o1.z + cb * acc2[r][6];
            w1.w = c_old * o1.w + cb * acc2[r][7];
            *(float4*)(out + base)     = w0;
            *(float4*)(out + base + 4) = w1;

            if ((t & 15) == 0)
                out[O_ELEMS + ((size_t)batch * HQ + h) * SEQ + s] = lse_new;
        }
    }

    // ---------------- dynamic copy of the remaining output regions ----------------
    while (true) {
        if (t == 0) s_chunk = atomicAdd(&g_chunk_counter, 1);
        __syncthreads();
        const int c = s_chunk;
        __syncthreads();
        if (c >= nChunkTotal) break;
        copy_chunk(cc, c, t);
    }
}

extern "C" void kernel_launch(void* const* d_in, const int* in_sizes, int n_in,
                              void* d_out, int out_size)
{
    const float* q    = (const float*)d_in[0];
    const float* k    = (const float*)d_in[1];
    const float* v    = (const float*)d_in[2];
    const float* go   = (const float*)d_in[3];
    const float* glse = (const float*)d_in[4];
    const float* gq   = (const float*)d_in[5];
    const float* gk   = (const float*)d_in[6];
    const int*   biq  = (const int*)d_in[7];
    const int*   bikv = (const int*)d_in[8];
    float* out = (float*)d_out;

    const int B = in_sizes[0] / (BQ * HQ * HD);           // 4
    const int nCompute    = B * HQ * 2;                   // 256
    const int nChunkO     = (B * (SEQ - BQ)) / ROWS_PER_CHUNK; // 1984
    const int nChunkTotal = nChunkO + B * HQ;             // +128 lse chunks

    const size_t smem = SMEM_FLOATS * sizeof(float);      // ~100.5 KB
    cudaFuncSetAttribute(oswa_fused_kernel,
                         cudaFuncAttributeMaxDynamicSharedMemorySize, (int)smem);

    const int grid = nCompute + 40;   // 296 = 2 CTAs/SM * 148 SMs (fill with pure-copy CTAs)

    init_counter_kernel<<<1, 1>>>();
    oswa_fused_kernel<<<grid, 256, smem>>>(q, k, v, go, glse, gq, gk, biq, bikv,
                                           out, B, nCompute, nChunkO, nChunkTotal);
}